// round 7
// baseline (speedup 1.0000x reference)
#include <cuda_runtime.h>
#include <cuda_bf16.h>
#include <cstdint>

#define FULL_MASK 0xFFFFFFFFu

#define NSTAGE     3
#define CHUNK      8192                    // output elems per chunk
#define NCHUNK     16                      // 131072 / 8192
#define FLIP_BYTES (CHUNK * 4)             // 32768
#define EDC_BYTES  (CHUNK * 4 + 16)        // 32784: covers 16B-align shift + boundary elem
#define STAGE_TX   (FLIP_BYTES + EDC_BYTES)

// dynamic smem layout (16B-aligned offsets)
#define OFF_MBAR   0                       // 3 x 8B mbarriers
#define OFF_WPAR   64                      // 32 x u32 packed warp parities (2 bits)
#define OFF_WEXCL  192                     // 32 x u32 packed exclusive scans (2 bits)
#define OFF_CARRY  320                     // 2 x u32 ping-pong carry
#define OFF_FLIPS  512
#define OFF_EDC    (OFF_FLIPS + NSTAGE * FLIP_BYTES)    // 98816
#define SMEM_BYTES (OFF_EDC + NSTAGE * EDC_BYTES)       // 197168

static __device__ __forceinline__ float fast_sqrt(float x) {
    float y; asm("sqrt.approx.f32 %0, %1;" : "=f"(y) : "f"(x)); return y;
}
static __device__ __forceinline__ float apply_sign(float a, unsigned neg) {
    return __uint_as_float(__float_as_uint(a) ^ (neg << 31));
}
static __device__ __forceinline__ void mbar_init(uint32_t mbar, uint32_t cnt) {
    asm volatile("mbarrier.init.shared.b64 [%0], %1;" :: "r"(mbar), "r"(cnt) : "memory");
}
static __device__ __forceinline__ void mbar_expect_tx(uint32_t mbar, uint32_t tx) {
    asm volatile("mbarrier.arrive.expect_tx.shared.b64 _, [%0], %1;" :: "r"(mbar), "r"(tx) : "memory");
}
static __device__ __forceinline__ void mbar_wait(uint32_t mbar, uint32_t phase) {
    uint32_t done;
    asm volatile("{\n\t.reg .pred p;\n\t"
                 "mbarrier.try_wait.parity.acquire.cta.shared::cta.b64 p, [%1], %2;\n\t"
                 "selp.b32 %0, 1, 0, p;\n\t}"
                 : "=r"(done) : "r"(mbar), "r"(phase) : "memory");
    if (!done) {
        asm volatile("{\n\t.reg .pred P1;\n\t"
                     "W_%=:\n\t"
                     "mbarrier.try_wait.parity.acquire.cta.shared::cta.b64 P1, [%0], %1, 0x989680;\n\t"
                     "@P1 bra.uni D_%=;\n\t"
                     "bra.uni W_%=;\n\t"
                     "D_%=:\n\t}"
                     :: "r"(mbar), "r"(phase) : "memory");
    }
}
static __device__ __forceinline__ void bulk_g2s(uint32_t dst, const void* src,
                                                uint32_t bytes, uint32_t mbar) {
    asm volatile("cp.async.bulk.shared::cluster.global.mbarrier::complete_tx::bytes "
                 "[%0], [%1], %2, [%3];"
                 :: "r"(dst), "l"(src), "r"(bytes), "r"(mbar) : "memory");
}

// Per-4-group helpers
static __device__ __forceinline__ unsigned group_bits(int4 fv) {
    return ((unsigned)fv.x & 1u) | (((unsigned)fv.y & 1u) << 1) |
           (((unsigned)fv.z & 1u) << 2) | (((unsigned)fv.w & 1u) << 3);
}

template <int O>
static __device__ __forceinline__ void pick5(float4 qa, float4 qb,
                                             float& e0, float& e1, float& e2,
                                             float& e3, float& e4) {
    if (O == 0)      { e0 = qa.x; e1 = qa.y; e2 = qa.z; e3 = qa.w; e4 = qb.x; }
    else if (O == 1) { e0 = qa.y; e1 = qa.z; e2 = qa.w; e3 = qb.x; e4 = qb.y; }
    else if (O == 2) { e0 = qa.z; e1 = qa.w; e2 = qb.x; e3 = qb.y; e4 = qb.z; }
    else             { e0 = qa.w; e1 = qb.x; e2 = qb.y; e3 = qb.z; e4 = qb.w; }
}

static __device__ __forceinline__ float4 signed_amp(float e0, float e1, float e2,
                                                    float e3, float e4,
                                                    unsigned g, unsigned neg) {
    unsigned incl = g;
    incl ^= incl << 1;
    incl ^= incl << 2;                     // inclusive prefix-XOR within the 4-group
    unsigned s = (incl ^ (neg ? 0xFu : 0u)) & 0xFu;
    float a0 = fast_sqrt(fmaxf(e0 - e1, 0.0f));
    float a1 = fast_sqrt(fmaxf(e1 - e2, 0.0f));
    float a2 = fast_sqrt(fmaxf(e2 - e3, 0.0f));
    float a3 = fast_sqrt(fmaxf(e3 - e4, 0.0f));
    float4 o;
    o.x = apply_sign(a0,  s       & 1u);
    o.y = apply_sign(a1, (s >> 1) & 1u);
    o.z = apply_sign(a2, (s >> 2) & 1u);
    o.w = apply_sign(a3, (s >> 3) & 1u);
    return o;
}

// Whole-row worker specialized on the row's 16B misalignment O.
template <int O>
static __device__ __forceinline__ void run_row(char* sm, uint32_t sbase,
                                               const char* edcAligned,
                                               const char* flipsRow,
                                               float4* out4row,
                                               int tid, int lane, int w)
{
    const unsigned lmask = (1u << lane) - 1u;
    uint32_t* sWarpPar  = (uint32_t*)(sm + OFF_WPAR);
    uint32_t* sWarpExcl = (uint32_t*)(sm + OFF_WEXCL);
    uint32_t* sCarry    = (uint32_t*)(sm + OFF_CARRY);

    int s = 0;
    unsigned ph = 0;

    #pragma unroll 1
    for (int c = 0; c < NCHUNK; c++) {
        const uint32_t mb = sbase + OFF_MBAR + s * 8;
        mbar_wait(mb, ph);                 // stage (flips+edc) resident

        // ---- flips: two 4-groups per thread (chunk halves), parity ballots ----
        const int4* fb = (const int4*)(sm + OFF_FLIPS + s * FLIP_BYTES);
        int4 fvA = fb[tid];
        int4 fvB = fb[1024 + tid];
        unsigned gA = group_bits(fvA);
        if (c == 0 && tid == 0) gA &= ~1u;             // flips[:,0] never applied
        unsigned gB = group_bits(fvB);
        unsigned gpA = (gA ^ (gA >> 1) ^ (gA >> 2) ^ (gA >> 3)) & 1u;
        unsigned gpB = (gB ^ (gB >> 1) ^ (gB >> 2) ^ (gB >> 3)) & 1u;

        unsigned balA = __ballot_sync(FULL_MASK, gpA);
        unsigned balB = __ballot_sync(FULL_MASK, gpB);
        unsigned laneExclA = (unsigned)__popc(balA & lmask) & 1u;
        unsigned laneExclB = (unsigned)__popc(balB & lmask) & 1u;
        if (lane == 0)
            sWarpPar[w] = ((unsigned)__popc(balA) & 1u) |
                          (((unsigned)__popc(balB) & 1u) << 1);
        __syncthreads();                   // A: warp parities visible

        // ---- warp0: block scan over 64 ordered parities (h0 w0..31, h1 w0..31) ----
        if (w == 0) {
            unsigned pk  = sWarpPar[lane];
            unsigned b0w = __ballot_sync(FULL_MASK, pk & 1u);
            unsigned b1w = __ballot_sync(FULL_MASK, (pk >> 1) & 1u);
            unsigned h0all = (unsigned)__popc(b0w) & 1u;
            unsigned ex0 = (unsigned)__popc(b0w & lmask) & 1u;
            unsigned ex1 = (h0all ^ (unsigned)__popc(b1w & lmask)) & 1u;
            sWarpExcl[lane] = ex0 | (ex1 << 1);
            if (lane == 0)
                sCarry[(c + 1) & 1] = sCarry[c & 1] ^ h0all ^ ((unsigned)__popc(b1w) & 1u);
        }

        // ---- all warps: edc loads + amplitudes (independent of the scan) ----
        const float4* eb = (const float4*)(sm + OFF_EDC + s * EDC_BYTES);
        float4 qa0 = eb[tid];
        float4 qb0 = eb[tid + 1];
        float4 qa1 = eb[1024 + tid];
        float4 qb1 = eb[1024 + tid + 1];
        float e0A, e1A, e2A, e3A, e4A, e0B, e1B, e2B, e3B, e4B;
        pick5<O>(qa0, qb0, e0A, e1A, e2A, e3A, e4A);
        pick5<O>(qa1, qb1, e0B, e1B, e2B, e3B, e4B);

        __syncthreads();                   // B: scan done + stage fully consumed

        const unsigned carryIn = sCarry[c & 1];
        const unsigned ex = sWarpExcl[w];
        const unsigned negA = (carryIn ^ ex ^ laneExclA) & 1u;
        const unsigned negB = (carryIn ^ (ex >> 1) ^ laneExclB) & 1u;

        // refill this stage now that all reads are done (tid 0 only)
        if (tid == 0) {
            int n = c + NSTAGE;
            if (n < NCHUNK) {
                mbar_expect_tx(mb, STAGE_TX);
                bulk_g2s(sbase + OFF_FLIPS + s * FLIP_BYTES,
                         flipsRow + (size_t)n * FLIP_BYTES, FLIP_BYTES, mb);
                bulk_g2s(sbase + OFF_EDC + s * EDC_BYTES,
                         edcAligned + (size_t)n * (CHUNK * 4), EDC_BYTES, mb);
            }
        }

        out4row[c * 2048 + tid]        = signed_amp(e0A, e1A, e2A, e3A, e4A, gA, negA);
        out4row[c * 2048 + 1024 + tid] = signed_amp(e0B, e1B, e2B, e3B, e4B, gB, negB);

        if (++s == NSTAGE) { s = 0; ph ^= 1u; }
    }
}

// One block per row. 1024 threads; 3-stage cp.async.bulk pipeline with 8192-elem
// chunks keeps ~196KB/SM of loads in flight; 2 block barriers per chunk.
__global__ __launch_bounds__(1024, 1)
void SignStickyPhaseReconstructor_kernel(const float* __restrict__ edc,
                                         const int*   __restrict__ flips,
                                         float*       __restrict__ out)
{
    extern __shared__ char sm[];
    const uint32_t sbase = (uint32_t)__cvta_generic_to_shared(sm);

    const int tid  = threadIdx.x;
    const int lane = tid & 31;
    const int w    = tid >> 5;
    const int row  = blockIdx.x;

    const char* edcRow = (const char*)(edc + (size_t)row * 131073);
    const uintptr_t ea = (uintptr_t)edcRow;
    const char* edcAligned = (const char*)(ea & ~(uintptr_t)15);
    const int o = (int)((ea & 15) >> 2);             // 0..3, uniform per block
    const char* flipsRow = (const char*)(flips + (size_t)row * 131072);
    float4* out4row = (float4*)(out + (size_t)row * 131072);

    if (tid == 0) {
        #pragma unroll
        for (int s = 0; s < NSTAGE; s++) mbar_init(sbase + OFF_MBAR + s * 8, 1);
        ((uint32_t*)(sm + OFF_CARRY))[0] = 0u;
        ((uint32_t*)(sm + OFF_CARRY))[1] = 0u;
    }
    __syncthreads();
    if (tid == 0) {
        asm volatile("fence.proxy.async.shared::cta;" ::: "memory");
        #pragma unroll
        for (int n = 0; n < NSTAGE; n++) {
            uint32_t mb = sbase + OFF_MBAR + n * 8;
            mbar_expect_tx(mb, STAGE_TX);
            bulk_g2s(sbase + OFF_FLIPS + n * FLIP_BYTES,
                     flipsRow + (size_t)n * FLIP_BYTES, FLIP_BYTES, mb);
            bulk_g2s(sbase + OFF_EDC + n * EDC_BYTES,
                     edcAligned + (size_t)n * (CHUNK * 4), EDC_BYTES, mb);
        }
    }

    switch (o) {
        case 0:  run_row<0>(sm, sbase, edcAligned, flipsRow, out4row, tid, lane, w); break;
        case 1:  run_row<1>(sm, sbase, edcAligned, flipsRow, out4row, tid, lane, w); break;
        case 2:  run_row<2>(sm, sbase, edcAligned, flipsRow, out4row, tid, lane, w); break;
        default: run_row<3>(sm, sbase, edcAligned, flipsRow, out4row, tid, lane, w); break;
    }
}

extern "C" void kernel_launch(void* const* d_in, const int* in_sizes, int n_in,
                              void* d_out, int out_size)
{
    const int B = 256, T = 131073;

    const float* edc;
    const int*   flips;
    if (in_sizes[0] == B * T) {
        edc   = (const float*)d_in[0];
        flips = (const int*)  d_in[1];
    } else {
        edc   = (const float*)d_in[1];
        flips = (const int*)  d_in[0];
    }
    float* out = (float*)d_out;

    cudaFuncSetAttribute(SignStickyPhaseReconstructor_kernel,
                         cudaFuncAttributeMaxDynamicSharedMemorySize, SMEM_BYTES);
    SignStickyPhaseReconstructor_kernel<<<B, 1024, SMEM_BYTES>>>(edc, flips, out);
}